// round 15
// baseline (speedup 1.0000x reference)
#include <cuda_runtime.h>
#include <cuda_fp16.h>
#include <cstdint>

#define FDIM 64
#define TPB  256         // 8 warps: 4 tiles x warp-pair
#define RPC  128         // rows per CTA (4 tiles x 32 rows)
#define AMAX 48
#define TLEN 2048
#define WSTR 36          // uint2 stride per n-row of W tiles
#define XSTR 36          // uint2 stride per colpair of exchange tiles

#define SM_W 0                              // 2*64*36*8 = 36864
#define SM_S 36864                          // scores: 48*128*4 = 24576
#define SM_P (SM_S + AMAX*RPC*4)            // 61440: partials 8 warps * 32 floats
#define SM_X (SM_P + 1024)                  // 62464: 4 tiles * 32cp * 36 * 8
#define SMEM_TOTAL (SM_X + 4*32*XSTR*8)     // 99328 B -> 2 CTAs/SM

// sigmoid(x) = 0.5 + 0.5*tanh(x/2): single MUFU op, deterministic
__device__ __forceinline__ float sigmoidf(float x) {
    float h = 0.5f * x, t;
    asm("tanh.approx.f32 %0, %1;" : "=f"(t) : "f"(h));
    return fmaf(0.5f, t, 0.5f);
}

// split fp32 pair into packed fp16 hi + fp16 residual lo (e0 -> low half)
__device__ __forceinline__ void split_pack(float e0, float e1,
                                           uint32_t& hi, uint32_t& lo) {
    __half2 hp = __floats2half2_rn(e0, e1);
    float f0 = __low2float(hp), f1 = __high2float(hp);
    __half2 lp = __floats2half2_rn(e0 - f0, e1 - f1);
    hi = *reinterpret_cast<uint32_t*>(&hp);
    lo = *reinterpret_cast<uint32_t*>(&lp);
}

#define MMA16(d,a,b0,b1) \
    asm("mma.sync.aligned.m16n8k16.row.col.f32.f16.f16.f32 " \
        "{%0,%1,%2,%3},{%4,%5,%6,%7},{%8,%9},{%0,%1,%2,%3};" \
        : "+f"((d)[0]),"+f"((d)[1]),"+f"((d)[2]),"+f"((d)[3]) \
        : "r"((a)[0]),"r"((a)[1]),"r"((a)[2]),"r"((a)[3]),"r"(b0),"r"(b1))

// Half-GEMM, one 16-row m-tile: d[nt][c] = H(16 rows, frag Ahi/Alo) @ Wcols(half*32..+31)
// 4 accumulator chains, dep distance 4 between same-chain MMAs.
__device__ __forceinline__ void gemm_half(float (&d)[4][4],
                                          const uint32_t (&Ahi)[4][4],
                                          const uint32_t (&Alo)[4][4],
                                          const uint2* __restrict__ sWm,
                                          int half, int r, int q)
{
    #pragma unroll
    for (int nt = 0; nt < 4; nt++)
        #pragma unroll
        for (int c = 0; c < 4; c++) d[nt][c] = 0.0f;

    #pragma unroll
    for (int kt = 0; kt < 4; kt++) {
        uint2 u[4][2];
        #pragma unroll
        for (int nt = 0; nt < 4; nt++) {
            const uint2* bp = sWm + (half * 32 + nt * 8 + r) * WSTR + q;
            u[nt][0] = bp[8 * kt];
            u[nt][1] = bp[8 * kt + 4];
        }
        #pragma unroll
        for (int nt = 0; nt < 4; nt++) MMA16(d[nt], Ahi[kt], u[nt][0].x, u[nt][1].x);
        #pragma unroll
        for (int nt = 0; nt < 4; nt++) MMA16(d[nt], Alo[kt], u[nt][0].x, u[nt][1].x);
        #pragma unroll
        for (int nt = 0; nt < 4; nt++) MMA16(d[nt], Ahi[kt], u[nt][0].y, u[nt][1].y);
    }
}

extern __shared__ char smem_raw[];

__global__ void __launch_bounds__(TPB, 2) ContextBlock_kernel(
    const float* __restrict__ he,
    const float* __restrict__ W1,
    const float* __restrict__ W2,
    const int*   __restrict__ alen,
    float*       __restrict__ out,
    int n_rows)
{
    const int tid  = threadIdx.x;
    const int lane = tid & 31;
    const int wid  = tid >> 5;
    const int q    = lane & 3;
    const int r    = lane >> 2;
    const int pairid = wid >> 1;     // tile id 0..3
    const int half   = wid & 1;      // n-half of this warp

    uint2* sW  = (uint2*)(smem_raw + SM_W);
    float* sS  = (float*)(smem_raw + SM_S);
    float* sP  = (float*)(smem_raw + SM_P);
    uint2* sX  = (uint2*)(smem_raw + SM_X) + pairid * (32 * XSTR);

    // ---- W prep: pre-split hi/lo fp16 pairs, B-fragment layout [m][n][kpair] ----
    for (int i = tid; i < 2 * 64 * 32; i += TPB) {
        int m   = i >> 11;
        int rem = i & 2047;
        int n = rem >> 5, kp = rem & 31;
        const float* W = m ? W2 : W1;
        float w0 = W[(2 * kp) * FDIM + n];
        float w1 = W[(2 * kp + 1) * FDIM + n];
        uint2 u;
        split_pack(w0, w1, u.x, u.y);
        sW[m * 64 * WSTR + n * WSTR + kp] = u;
    }

    // ---- identity ----
    const int ctaRow0 = blockIdx.x * RPC;
    const int t0cta   = ctaRow0 % TLEN;
    const float* bhe  = he + (size_t)(ctaRow0 - t0cta) * FDIM;
    const int tileRow0 = ctaRow0 + pairid * 32;

    int A = alen ? alen[0] : AMAX;
    if (A > AMAX) A = AMAX;

    // ---- init register-resident H state (32 rows/tile; both pair warps same) ----
    uint32_t Ahi[2][4][4], Alo[2][4][4];
    #pragma unroll
    for (int mt = 0; mt < 2; mt++) {
        const int R0 = min(tileRow0 + r + 16 * mt, n_rows - 1);
        const int R1 = min(R0 + 8, n_rows - 1);
        const float* p0 = he + (size_t)R0 * FDIM;
        const float* p1 = he + (size_t)R1 * FDIM;
        #pragma unroll
        for (int kt = 0; kt < 4; kt++) {
            int c0 = 16 * kt + 2 * q, c1 = c0 + 8;
            float2 e;
            e = *(const float2*)(p0 + c0); split_pack(e.x, e.y, Ahi[mt][kt][0], Alo[mt][kt][0]);
            e = *(const float2*)(p1 + c0); split_pack(e.x, e.y, Ahi[mt][kt][1], Alo[mt][kt][1]);
            e = *(const float2*)(p0 + c1); split_pack(e.x, e.y, Ahi[mt][kt][2], Alo[mt][kt][2]);
            e = *(const float2*)(p1 + c1); split_pack(e.x, e.y, Ahi[mt][kt][3], Alo[mt][kt][3]);
        }
    }

    // ---- per-warp attention params for score rows r+8m ----
    int basem[4];
    #pragma unroll
    for (int m = 0; m < 4; m++) {
        int tm = (tileRow0 + r + 8 * m) % TLEN;
        basem[m] = tm - min(A, max(tm, 1));
    }
    __syncthreads();   // W tiles ready

    // ================= Pass 1: recurrence + scores =================
    for (int a = 0; a < AMAX; a++) {
        // ---- GEMM1 (my n-half): H' = sigmoid(H @ W1) -> packed exchange store ----
        #pragma unroll
        for (int mt = 0; mt < 2; mt++) {
            float d[4][4];
            gemm_half(d, Ahi[mt], Alo[mt], sW, half, r, q);
            #pragma unroll
            for (int nt = 0; nt < 4; nt++) {
                const int cp = half * 16 + nt * 4 + q;
                uint2 u;
                split_pack(sigmoidf(d[nt][0]), sigmoidf(d[nt][1]), u.x, u.y);
                sX[cp * XSTR + (r + 16 * mt)] = u;
                split_pack(sigmoidf(d[nt][2]), sigmoidf(d[nt][3]), u.x, u.y);
                sX[cp * XSTR + (r + 16 * mt + 8)] = u;
            }
        }
        __syncthreads();   // B1: exchange stores visible

        // ---- load full H' into A fragments ----
        #pragma unroll
        for (int mt = 0; mt < 2; mt++)
            #pragma unroll
            for (int kt = 0; kt < 4; kt++) {
                const int row0 = r + 16 * mt;
                uint2 u;
                u = sX[(8 * kt + q) * XSTR + row0];
                Ahi[mt][kt][0] = u.x; Alo[mt][kt][0] = u.y;
                u = sX[(8 * kt + q) * XSTR + row0 + 8];
                Ahi[mt][kt][1] = u.x; Alo[mt][kt][1] = u.y;
                u = sX[(8 * kt + q + 4) * XSTR + row0];
                Ahi[mt][kt][2] = u.x; Alo[mt][kt][2] = u.y;
                u = sX[(8 * kt + q + 4) * XSTR + row0 + 8];
                Ahi[mt][kt][3] = u.x; Alo[mt][kt][3] = u.y;
            }

        // ---- GEMM2 (my n-half): Y = sigmoid(H' @ W2); partial score over my cols ----
        float p[4] = {0.f, 0.f, 0.f, 0.f};
        #pragma unroll
        for (int mt = 0; mt < 2; mt++) {
            float d[4][4];
            gemm_half(d, Ahi[mt], Alo[mt], sW + 64 * WSTR, half, r, q);
            #pragma unroll
            for (int mloc = 0; mloc < 2; mloc++) {
                const int m = 2 * mt + mloc;
                const float* g = bhe + (size_t)max(basem[m] + a, 0) * FDIM
                                     + half * 32 + 2 * q;
                #pragma unroll
                for (int nt = 0; nt < 4; nt++) {
                    float y0 = sigmoidf(d[nt][2 * mloc + 0]);
                    float y1 = sigmoidf(d[nt][2 * mloc + 1]);
                    float2 gv = *(const float2*)(g + nt * 8);
                    p[m] = fmaf(y0, gv.x, fmaf(y1, gv.y, p[m]));
                }
            }
        }
        #pragma unroll
        for (int m = 0; m < 4; m++) {
            p[m] += __shfl_xor_sync(0xFFFFFFFFu, p[m], 1);
            p[m] += __shfl_xor_sync(0xFFFFFFFFu, p[m], 2);
        }
        if (q == 0) {
            #pragma unroll
            for (int m = 0; m < 4; m++) sP[wid * 32 + r * 4 + m] = p[m];
        }
        __syncthreads();   // B2: partials visible

        // ---- combine pair partials -> sS (even warp, one lane per (r,m)) ----
        if ((wid & 1) == 0) {
            const int r2 = lane >> 2, m2 = lane & 3;
            const int rloc = r2 + 8 * m2;                 // 0..31 distinct
            const int t2 = (tileRow0 + rloc) % TLEN;
            const int L2 = min(A, max(t2, 1));
            float s = sP[wid * 32 + lane] + sP[(wid + 1) * 32 + lane];
            sS[a * RPC + pairid * 32 + rloc] = (a < L2) ? s : -1e30f;
        }
        __syncthreads();   // B3: sP reads done before next-step overwrite
    }

    // ================= Pass 2: softmax + gather; 2 threads per row =============
    {
        const int rowIdx = tid & 127;
        const int fhalf  = tid >> 7;
        const int row    = ctaRow0 + rowIdx;
        if (row < n_rows) {
            const int t   = row % TLEN;
            const int L   = min(A, max(t, 1));
            const int bse = t - L;

            float mx = -1e30f;
            for (int a = 0; a < AMAX; a++) mx = fmaxf(mx, sS[a * RPC + rowIdx]);

            float acc[32];
            #pragma unroll
            for (int j = 0; j < 32; j++) acc[j] = 0.0f;
            float ssum = 0.0f;
            const float* gb = bhe + fhalf * 32;
            for (int a = 0; a < L; a++) {
                float w = __expf(sS[a * RPC + rowIdx] - mx);
                ssum += w;
                int jrow = max(bse + a, 0);
                const float4* g = (const float4*)(gb + (size_t)jrow * FDIM);
                #pragma unroll
                for (int c = 0; c < 8; c++) {
                    float4 gv = g[c];
                    acc[4*c+0] = fmaf(w, gv.x, acc[4*c+0]);
                    acc[4*c+1] = fmaf(w, gv.y, acc[4*c+1]);
                    acc[4*c+2] = fmaf(w, gv.z, acc[4*c+2]);
                    acc[4*c+3] = fmaf(w, gv.w, acc[4*c+3]);
                }
            }
            const float inv = __fdividef(1.0f, ssum);
            float4* o = (float4*)(out + (size_t)row * FDIM + fhalf * 32);
            #pragma unroll
            for (int c = 0; c < 8; c++) {
                float4 v;
                v.x = acc[4*c+0] * inv; v.y = acc[4*c+1] * inv;
                v.z = acc[4*c+2] * inv; v.w = acc[4*c+3] * inv;
                o[c] = v;
            }
        }
    }
}

extern "C" void kernel_launch(void* const* d_in, const int* in_sizes, int n_in,
                              void* d_out, int out_size)
{
    const float* he   = (const float*)d_in[0];
    const float* W1   = (const float*)d_in[1];
    const float* W2   = (const float*)d_in[2];
    const int*   alen = (n_in >= 4) ? (const int*)d_in[3] : nullptr;
    float*       out  = (float*)d_out;

    const int n_rows = in_sizes[0] / FDIM;   // B*T

    cudaFuncSetAttribute(ContextBlock_kernel,
                         cudaFuncAttributeMaxDynamicSharedMemorySize, SMEM_TOTAL);
    const int grid = (n_rows + RPC - 1) / RPC;
    ContextBlock_kernel<<<grid, TPB, SMEM_TOTAL>>>(he, W1, W2, alen, out, n_rows);
}

// round 16
// speedup vs baseline: 1.4631x; 1.4631x over previous
#include <cuda_runtime.h>
#include <cuda_fp16.h>
#include <cstdint>

#define FDIM 64
#define TPB  128
#define RPC  128         // rows per CTA (4 warps x 32 rows)
#define AMAX 48
#define TLEN 2048
#define WSTR 36          // uint2 stride per n-row of W tiles (4r+q bank-distinct)

#define SM_W 0
#define SM_S (2*64*WSTR*8)             // 36864
#define SM_N (SM_S + AMAX*RPC*4)       // 61440 ; per-warp 8KB packed N buffer
#define SMEM_TOTAL (SM_N + 4*32*32*8)  // 94208

// compiler-only memory barrier: stops cross-chunk LDS hoisting (reg-pressure control)
#define OPT_BARRIER() asm volatile("" ::: "memory")

// sigmoid(x) = 0.5 + 0.5*tanh(x/2): single MUFU op, deterministic
__device__ __forceinline__ float sigmoidf(float x) {
    float h = 0.5f * x, t;
    asm("tanh.approx.f32 %0, %1;" : "=f"(t) : "f"(h));
    return fmaf(0.5f, t, 0.5f);
}

// split fp32 pair into packed fp16 hi + fp16 residual lo (e0 -> low half)
__device__ __forceinline__ void split_pack(float e0, float e1,
                                           uint32_t& hi, uint32_t& lo) {
    __half2 hp = __floats2half2_rn(e0, e1);
    float f0 = __low2float(hp), f1 = __high2float(hp);
    __half2 lp = __floats2half2_rn(e0 - f0, e1 - f1);
    hi = *reinterpret_cast<uint32_t*>(&hp);
    lo = *reinterpret_cast<uint32_t*>(&lp);
}

#define MMA16(d,a,b0,b1) \
    asm("mma.sync.aligned.m16n8k16.row.col.f32.f16.f16.f32 " \
        "{%0,%1,%2,%3},{%4,%5,%6,%7},{%8,%9},{%0,%1,%2,%3};" \
        : "+f"((d)[0]),"+f"((d)[1]),"+f"((d)[2]),"+f"((d)[3]) \
        : "r"((a)[0]),"r"((a)[1]),"r"((a)[2]),"r"((a)[3]),"r"(b0),"r"(b1))

// Dual-matrix nt-pair chunk: d1 += A@W1cols, d2 += A@W2cols interleaved (8 chains)
__device__ __forceinline__ void dual_chunk(float (&d1)[2][2][4],
                                           float (&d2)[2][2][4],
                                           const uint32_t (&Ahi)[2][4][4],
                                           const uint32_t (&Alo)[2][4][4],
                                           const uint2* __restrict__ sW1,
                                           const uint2* __restrict__ sW2,
                                           int ntp, int r, int q)
{
    #pragma unroll
    for (int mt = 0; mt < 2; mt++)
        #pragma unroll
        for (int np = 0; np < 2; np++)
            #pragma unroll
            for (int c = 0; c < 4; c++) { d1[mt][np][c] = 0.0f; d2[mt][np][c] = 0.0f; }

    const uint2* ap0 = sW1 + (16 * ntp + r) * WSTR + q;
    const uint2* ap1 = sW1 + (16 * ntp + 8 + r) * WSTR + q;
    const uint2* bp0 = sW2 + (16 * ntp + r) * WSTR + q;
    const uint2* bp1 = sW2 + (16 * ntp + 8 + r) * WSTR + q;
    #pragma unroll
    for (int kt = 0; kt < 4; kt++) {
        uint2 u00 = ap0[8 * kt], u01 = ap0[8 * kt + 4];
        uint2 u10 = ap1[8 * kt], u11 = ap1[8 * kt + 4];
        uint2 v00 = bp0[8 * kt], v01 = bp0[8 * kt + 4];
        uint2 v10 = bp1[8 * kt], v11 = bp1[8 * kt + 4];
        MMA16(d1[0][0], Ahi[0][kt], u00.x, u01.x);
        MMA16(d1[0][1], Ahi[0][kt], u10.x, u11.x);
        MMA16(d1[1][0], Ahi[1][kt], u00.x, u01.x);
        MMA16(d1[1][1], Ahi[1][kt], u10.x, u11.x);
        MMA16(d2[0][0], Ahi[0][kt], v00.x, v01.x);
        MMA16(d2[0][1], Ahi[0][kt], v10.x, v11.x);
        MMA16(d2[1][0], Ahi[1][kt], v00.x, v01.x);
        MMA16(d2[1][1], Ahi[1][kt], v10.x, v11.x);
        MMA16(d1[0][0], Alo[0][kt], u00.x, u01.x);
        MMA16(d1[0][1], Alo[0][kt], u10.x, u11.x);
        MMA16(d1[1][0], Alo[1][kt], u00.x, u01.x);
        MMA16(d1[1][1], Alo[1][kt], u10.x, u11.x);
        MMA16(d2[0][0], Alo[0][kt], v00.x, v01.x);
        MMA16(d2[0][1], Alo[0][kt], v10.x, v11.x);
        MMA16(d2[1][0], Alo[1][kt], v00.x, v01.x);
        MMA16(d2[1][1], Alo[1][kt], v10.x, v11.x);
        MMA16(d1[0][0], Ahi[0][kt], u00.y, u01.y);
        MMA16(d1[0][1], Ahi[0][kt], u10.y, u11.y);
        MMA16(d1[1][0], Ahi[1][kt], u00.y, u01.y);
        MMA16(d1[1][1], Ahi[1][kt], u10.y, u11.y);
        MMA16(d2[0][0], Ahi[0][kt], v00.y, v01.y);
        MMA16(d2[0][1], Ahi[0][kt], v10.y, v11.y);
        MMA16(d2[1][0], Ahi[1][kt], v00.y, v01.y);
        MMA16(d2[1][1], Ahi[1][kt], v10.y, v11.y);
    }
}

// W1-only chunk (prologue)
__device__ __forceinline__ void gemm_chunk(float (&dd)[2][2][4],
                                           const uint32_t (&Ahi)[2][4][4],
                                           const uint32_t (&Alo)[2][4][4],
                                           const uint2* __restrict__ sWm,
                                           int ntp, int r, int q)
{
    #pragma unroll
    for (int mt = 0; mt < 2; mt++)
        #pragma unroll
        for (int np = 0; np < 2; np++)
            #pragma unroll
            for (int c = 0; c < 4; c++) dd[mt][np][c] = 0.0f;

    const uint2* bp0 = sWm + (16 * ntp + r) * WSTR + q;
    const uint2* bp1 = sWm + (16 * ntp + 8 + r) * WSTR + q;
    #pragma unroll
    for (int kt = 0; kt < 4; kt++) {
        uint2 u00 = bp0[8 * kt], u01 = bp0[8 * kt + 4];
        uint2 u10 = bp1[8 * kt], u11 = bp1[8 * kt + 4];
        MMA16(dd[0][0], Ahi[0][kt], u00.x, u01.x);
        MMA16(dd[0][1], Ahi[0][kt], u10.x, u11.x);
        MMA16(dd[1][0], Ahi[1][kt], u00.x, u01.x);
        MMA16(dd[1][1], Ahi[1][kt], u10.x, u11.x);
        MMA16(dd[0][0], Alo[0][kt], u00.x, u01.x);
        MMA16(dd[0][1], Alo[0][kt], u10.x, u11.x);
        MMA16(dd[1][0], Alo[1][kt], u00.x, u01.x);
        MMA16(dd[1][1], Alo[1][kt], u10.x, u11.x);
        MMA16(dd[0][0], Ahi[0][kt], u00.y, u01.y);
        MMA16(dd[0][1], Ahi[0][kt], u10.y, u11.y);
        MMA16(dd[1][0], Ahi[1][kt], u00.y, u01.y);
        MMA16(dd[1][1], Ahi[1][kt], u10.y, u11.y);
    }
}

extern __shared__ char smem_raw[];

__global__ void __launch_bounds__(TPB) ContextBlock_kernel(
    const float* __restrict__ he,
    const float* __restrict__ W1,
    const float* __restrict__ W2,
    const int*   __restrict__ alen,
    float*       __restrict__ out,
    int n_rows)
{
    const int tid  = threadIdx.x;
    const int lane = tid & 31;
    const int wid  = tid >> 5;
    const int q    = lane & 3;
    const int r    = lane >> 2;

    uint2* sW  = (uint2*)(smem_raw + SM_W);
    float* sS  = (float*)(smem_raw + SM_S);
    uint2* sNw = (uint2*)(smem_raw + SM_N) + wid * (32 * 32) + lane;  // lane base

    // ---- W prep: pre-split hi/lo fp16 pairs, B-fragment layout [m][n][kpair] ----
    for (int i = tid; i < 2 * 64 * 32; i += TPB) {
        int m   = i >> 11;
        int rem = i & 2047;
        int n = rem >> 5, kp = rem & 31;
        const float* W = m ? W2 : W1;
        float w0 = W[(2 * kp) * FDIM + n];
        float w1 = W[(2 * kp + 1) * FDIM + n];
        uint2 u;
        split_pack(w0, w1, u.x, u.y);
        sW[m * 64 * WSTR + n * WSTR + kp] = u;
    }

    // ---- identity ----
    const int ctaRow0 = blockIdx.x * RPC;
    const int t0cta   = ctaRow0 % TLEN;
    const float* bhe  = he + (size_t)(ctaRow0 - t0cta) * FDIM;

    int A = alen ? alen[0] : AMAX;
    if (A > AMAX) A = AMAX;

    // ---- init register-resident H state (32 rows/warp) from he ----
    const int warpRow = ctaRow0 + wid * 32;
    uint32_t Ahi[2][4][4], Alo[2][4][4];
    #pragma unroll
    for (int mt = 0; mt < 2; mt++) {
        const int R0 = min(warpRow + r + 16 * mt, n_rows - 1);
        const int R1 = min(R0 + 8, n_rows - 1);
        const float* p0 = he + (size_t)R0 * FDIM;
        const float* p1 = he + (size_t)R1 * FDIM;
        #pragma unroll
        for (int kt = 0; kt < 4; kt++) {
            int c0 = 16 * kt + 2 * q, c1 = c0 + 8;
            float2 e;
            e = *(const float2*)(p0 + c0); split_pack(e.x, e.y, Ahi[mt][kt][0], Alo[mt][kt][0]);
            e = *(const float2*)(p1 + c0); split_pack(e.x, e.y, Ahi[mt][kt][1], Alo[mt][kt][1]);
            e = *(const float2*)(p0 + c1); split_pack(e.x, e.y, Ahi[mt][kt][2], Alo[mt][kt][2]);
            e = *(const float2*)(p1 + c1); split_pack(e.x, e.y, Ahi[mt][kt][3], Alo[mt][kt][3]);
        }
    }
    __syncthreads();   // W tiles ready

    // ---- per-epi-row attention params (rows r+8m of warp block) ----
    int Lm[4], basem[4];
    #pragma unroll
    for (int m = 0; m < 4; m++) {
        int grow = warpRow + r + 8 * m;
        int tm = grow % TLEN;
        int Lv = min(A, max(tm, 1));
        Lm[m] = Lv;
        basem[m] = tm - Lv;
    }

    // ---- prologue: N = sigmoid-split(H0 @ W1), packed into per-warp smem ----
    #pragma unroll
    for (int ntp = 0; ntp < 4; ntp++) {
        OPT_BARRIER();
        float dd[2][2][4];
        gemm_chunk(dd, Ahi, Alo, sW, ntp, r, q);
        #pragma unroll
        for (int mt = 0; mt < 2; mt++) {
            uint2 u;
            split_pack(sigmoidf(dd[mt][0][0]), sigmoidf(dd[mt][0][1]), u.x, u.y);
            sNw[(ntp * 8 + mt * 4 + 0) * 32] = u;
            split_pack(sigmoidf(dd[mt][0][2]), sigmoidf(dd[mt][0][3]), u.x, u.y);
            sNw[(ntp * 8 + mt * 4 + 1) * 32] = u;
            split_pack(sigmoidf(dd[mt][1][0]), sigmoidf(dd[mt][1][1]), u.x, u.y);
            sNw[(ntp * 8 + mt * 4 + 2) * 32] = u;
            split_pack(sigmoidf(dd[mt][1][2]), sigmoidf(dd[mt][1][3]), u.x, u.y);
            sNw[(ntp * 8 + mt * 4 + 3) * 32] = u;
        }
        OPT_BARRIER();
    }

    // ================= Pass 1: recurrence + scores =================
    for (int a = 0; a < AMAX; a++) {
        // ---- load A <- N (packed per-warp smem; warp-synchronous) ----
        #pragma unroll
        for (int mt = 0; mt < 2; mt++)
            #pragma unroll
            for (int kt = 0; kt < 4; kt++)
                #pragma unroll
                for (int idx = 0; idx < 4; idx++) {
                    uint2 u = sNw[(kt * 8 + mt * 4 + idx) * 32];
                    Ahi[mt][kt][idx] = u.x;
                    Alo[mt][kt][idx] = u.y;
                }
        OPT_BARRIER();

        const float* gp[4];
        #pragma unroll
        for (int m = 0; m < 4; m++) {
            int j = basem[m] + a;
            j = max(j, 0);
            gp[m] = bhe + (size_t)j * FDIM;
        }
        float p[4] = {0.f, 0.f, 0.f, 0.f};
        #pragma unroll
        for (int ntp = 0; ntp < 4; ntp++) {
            OPT_BARRIER();   // bound fragment liveness to this chunk
            float d1[2][2][4], d2[2][2][4];
            dual_chunk(d1, d2, Ahi, Alo, sW, sW + 64 * WSTR, ntp, r, q);
            // next-H chunk -> packed N store (A fully loaded above; safe overwrite)
            #pragma unroll
            for (int mt = 0; mt < 2; mt++) {
                uint2 u;
                split_pack(sigmoidf(d1[mt][0][0]), sigmoidf(d1[mt][0][1]), u.x, u.y);
                sNw[(ntp * 8 + mt * 4 + 0) * 32] = u;
                split_pack(sigmoidf(d1[mt][0][2]), sigmoidf(d1[mt][0][3]), u.x, u.y);
                sNw[(ntp * 8 + mt * 4 + 1) * 32] = u;
                split_pack(sigmoidf(d1[mt][1][0]), sigmoidf(d1[mt][1][1]), u.x, u.y);
                sNw[(ntp * 8 + mt * 4 + 2) * 32] = u;
                split_pack(sigmoidf(d1[mt][1][2]), sigmoidf(d1[mt][1][3]), u.x, u.y);
                sNw[(ntp * 8 + mt * 4 + 3) * 32] = u;
            }
            // score chunk
            #pragma unroll
            for (int np = 0; np < 2; np++) {
                const int col = (2 * ntp + np) * 8 + 2 * q;
                #pragma unroll
                for (int m = 0; m < 4; m++) {
                    int mt = m >> 1, cp = (m & 1) * 2;
                    float y0 = sigmoidf(d2[mt][np][cp + 0]);
                    float y1 = sigmoidf(d2[mt][np][cp + 1]);
                    float2 g = *(const float2*)(gp[m] + col);
                    p[m] = fmaf(y0, g.x, fmaf(y1, g.y, p[m]));
                }
            }
            OPT_BARRIER();
        }
        #pragma unroll
        for (int m = 0; m < 4; m++) {
            p[m] += __shfl_xor_sync(0xFFFFFFFFu, p[m], 1);
            p[m] += __shfl_xor_sync(0xFFFFFFFFu, p[m], 2);
        }
        if (q == 0) {
            #pragma unroll
            for (int m = 0; m < 4; m++)
                sS[a * RPC + wid * 32 + r + 8 * m] = (a < Lm[m]) ? p[m] : -1e30f;
        }
    }
    __syncthreads();

    // ================= Pass 2: softmax + weighted gather (1 thread/row) =========
    {
        const int row = ctaRow0 + tid;
        if (row < n_rows) {
            const int t   = row % TLEN;
            const int L   = min(A, max(t, 1));
            const int bse = t - L;

            float mx = -1e30f;
            for (int a = 0; a < AMAX; a++) mx = fmaxf(mx, sS[a * RPC + tid]);

            float acc[FDIM];
            #pragma unroll
            for (int j = 0; j < FDIM; j++) acc[j] = 0.0f;
            float ssum = 0.0f;
            for (int a = 0; a < L; a++) {
                float w = __expf(sS[a * RPC + tid] - mx);
                ssum += w;
                int jrow = max(bse + a, 0);
                const float4* g = (const float4*)(bhe + (size_t)jrow * FDIM);
                #pragma unroll
                for (int c = 0; c < 16; c++) {
                    float4 gv = g[c];
                    acc[4*c+0] = fmaf(w, gv.x, acc[4*c+0]);
                    acc[4*c+1] = fmaf(w, gv.y, acc[4*c+1]);
                    acc[4*c+2] = fmaf(w, gv.z, acc[4*c+2]);
                    acc[4*c+3] = fmaf(w, gv.w, acc[4*c+3]);
                }
            }
            const float inv = __fdividef(1.0f, ssum);
            float4* o = (float4*)(out + (size_t)row * FDIM);
            #pragma unroll
            for (int c = 0; c < 16; c++) {
                float4 v;
                v.x = acc[4*c+0] * inv; v.y = acc[4*c+1] * inv;
                v.z = acc[4*c+2] * inv; v.w = acc[4*c+3] * inv;
                o[c] = v;
            }
        }
    }
}

extern "C" void kernel_launch(void* const* d_in, const int* in_sizes, int n_in,
                              void* d_out, int out_size)
{
    const float* he   = (const float*)d_in[0];
    const float* W1   = (const float*)d_in[1];
    const float* W2   = (const float*)d_in[2];
    const int*   alen = (n_in >= 4) ? (const int*)d_in[3] : nullptr;
    float*       out  = (float*)d_out;

    const int n_rows = in_sizes[0] / FDIM;   // B*T

    cudaFuncSetAttribute(ContextBlock_kernel,
                         cudaFuncAttributeMaxDynamicSharedMemorySize, SMEM_TOTAL);
    const int grid = (n_rows + RPC - 1) / RPC;
    ContextBlock_kernel<<<grid, TPB, SMEM_TOTAL>>>(he, W1, W2, alen, out, n_rows);
}